// round 1
// baseline (speedup 1.0000x reference)
#include <cuda_runtime.h>

#define NP 262144
#define NR_OI 500
#define SUMH 224
#define SUMW 221

// ---------------- device scratch (no allocations allowed) ----------------
__device__ int    g_counts[NR_OI];
__device__ int    g_offsets[NR_OI + 1];
__device__ int    g_cursor[NR_OI];
__device__ int    g_perm[NP];
__device__ float2 g_ehw[NR_OI][SUMH];    // {exp(heights_emb), softmax width} per level-concatenated k
__device__ float  g_binloc[NR_OI][SUMH]; // bin locations per level-concatenated k (n entries per level)

// ---------------- grouping pre-pass ----------------
__global__ void k_zero() {
    int t = blockIdx.x * blockDim.x + threadIdx.x;
    if (t < NR_OI) g_counts[t] = 0;
}

__global__ void k_hist(const int* __restrict__ lrix) {
    int i = blockIdx.x * blockDim.x + threadIdx.x;
    if (i < NP) atomicAdd(&g_counts[lrix[i]], 1);
}

__global__ void k_scan() {
    __shared__ int s[512];
    int t = threadIdx.x;
    int v = (t < NR_OI) ? g_counts[t] : 0;
    s[t] = v;
    __syncthreads();
    for (int o = 1; o < 512; o <<= 1) {
        int a = (t >= o) ? s[t - o] : 0;
        __syncthreads();
        s[t] += a;
        __syncthreads();
    }
    if (t < NR_OI) {
        int ex = s[t] - v;
        g_offsets[t] = ex;
        g_cursor[t] = ex;
    }
    if (t == NR_OI - 1) g_offsets[NR_OI] = s[t];
}

__global__ void k_scatter(const int* __restrict__ lrix) {
    int i = blockIdx.x * blockDim.x + threadIdx.x;
    if (i < NP) {
        int pos = atomicAdd(&g_cursor[lrix[i]], 1);
        g_perm[pos] = i;
    }
}

// ---------------- per-region table prep ----------------
__device__ __forceinline__ float warp_max(float v) {
#pragma unroll
    for (int o = 16; o; o >>= 1) v = fmaxf(v, __shfl_xor_sync(0xffffffffu, v, o));
    return v;
}
__device__ __forceinline__ float warp_sum(float v) {
#pragma unroll
    for (int o = 16; o; o >>= 1) v += __shfl_xor_sync(0xffffffffu, v, o);
    return v;
}

template <int N, int OH, int OW>
__device__ __forceinline__ void prep_level(int r, int rid,
                                           const float* __restrict__ hemb,
                                           const float* __restrict__ wemb,
                                           float* sw) {
    const int M = N - 1;
    int lane = threadIdx.x;

    float vals[4];
    float mx = -1e30f;
#pragma unroll
    for (int j = 0; j < 4; j++) {
        int k = lane + 32 * j;
        vals[j] = (k < M) ? wemb[(size_t)rid * SUMW + OW + k] : -1e30f;
        mx = fmaxf(mx, vals[j]);
    }
    mx = warp_max(mx);

    float es[4];
    float sum = 0.f;
#pragma unroll
    for (int j = 0; j < 4; j++) {
        int k = lane + 32 * j;
        es[j] = (k < M) ? __expf(vals[j] - mx) : 0.f;
        sum += es[j];
    }
    sum = warp_sum(sum);
    float inv = 1.f / sum;

#pragma unroll
    for (int j = 0; j < 4; j++) {
        int k = lane + 32 * j;
        if (k < M) sw[k] = es[j] * inv;
    }
    __syncwarp();

    // exp(heights_emb) paired with width (width padded 0 at k = N-1)
#pragma unroll
    for (int j = 0; j < 4; j++) {
        int k = lane + 32 * j;
        if (k < N) {
            float eh = __expf(hemb[(size_t)rid * SUMH + OH + k]);
            float wk = (k < M) ? sw[k] : 0.f;
            g_ehw[r][OH + k] = make_float2(eh, wk);
        }
    }

    // serial cumsum for bin locations (tiny; one lane)
    if (lane == 0) {
        float c = 0.f;
        g_binloc[r][OH] = 0.f;
        for (int k = 1; k < N; k++) {
            c += sw[k - 1];
            g_binloc[r][OH + k] = (k == N - 1) ? 1.f : c;
        }
    }
    __syncwarp();
}

__global__ void k_prep(const int* __restrict__ roi,
                       const float* __restrict__ hemb,
                       const float* __restrict__ wemb) {
    __shared__ float sw[128];
    int r = blockIdx.x;
    int rid = roi[r];
    prep_level<128, 0, 0>(r, rid, hemb, wemb, sw);
    prep_level<64, 128, 127>(r, rid, hemb, wemb, sw);
    prep_level<32, 192, 190>(r, rid, hemb, wemb, sw);
}

// ---------------- main per-point kernel ----------------
template <int N, int OFF>
__device__ __forceinline__ void level_eval(float& xv, float& ld,
                                           const float* __restrict__ drow,
                                           const float2* __restrict__ sE,
                                           const float* __restrict__ sB) {
    const float2* E = sE + OFF;
    const float*  B = sB + OFF;

    // bin = clip(#(binloc < x) - 1, 0, N-2) via binary search on smem
    int lo = 0, hi = N;
    while (lo < hi) {
        int mid = (lo + hi) >> 1;
        if (B[mid] < xv) lo = mid + 1; else hi = mid;
    }
    int bin = lo - 1;
    bin = bin < 0 ? 0 : bin;
    bin = bin > N - 2 ? N - 2 : bin;

    const float4* d4 = reinterpret_cast<const float4*>(drow + OFF);

    float total = 0.f, partial = 0.f;
    float hl = 0.f, hr = 0.f;
    float heprev = 0.f, wprev = 0.f;  // wprev=0 makes first bogus term 0

#pragma unroll 4
    for (int c = 0; c < N / 4; c++) {
        float4 dv = __ldg(&d4[c]);
        float dd0 = dv.x, dd1 = dv.y, dd2 = dv.z, dd3 = dv.w;
#pragma unroll
        for (int j = 0; j < 4; j++) {
            int k = 4 * c + j;
            float d = (j == 0) ? dd0 : (j == 1) ? dd1 : (j == 2) ? dd2 : dd3;
            float2 e = E[k];
            float he = e.x * __expf(d);
            float t = (heprev + he) * wprev;  // raw trapezoid term (2x actual)
            total += t;
            int kk = k - 1;
            partial += (kk < bin) ? t : 0.f;
            if (kk == bin) { hl = heprev; hr = he; }
            heprev = he;
            wprev = e.y;
        }
    }

    float inv_t = __fdividef(1.f, total);
    float Hl = 2.f * hl * inv_t;       // he[bin]   / area, area = 0.5*total
    float Hr = 2.f * hr * inv_t;       // he[bin+1] / area
    float incdf = partial * inv_t;     // partial/total == 0.5*partial / area
    float inloc = B[bin];
    float w = E[bin].y;
    float alpha = (xv - inloc) * __fdividef(1.f, w);
    float dh = Hr - Hl;
    // out = 0.5*dh*w*a^2 + Hl*w*a + incdf
    xv = (0.5f * dh * alpha + Hl) * (w * alpha) + incdf;
    ld += __logf(fmaf(alpha, dh, Hl));
}

__global__ void __launch_bounds__(128)
k_main(const float* __restrict__ x,
       const float* __restrict__ delta,
       float* __restrict__ out) {
    __shared__ float2 sE[SUMH];
    __shared__ float  sB[SUMH];

    int r = blockIdx.x;
    for (int i = threadIdx.x; i < SUMH; i += blockDim.x) {
        sE[i] = g_ehw[r][i];
        sB[i] = g_binloc[r][i];
    }
    __syncthreads();

    int beg = g_offsets[r];
    int end = g_offsets[r + 1];

    for (int j = beg + blockIdx.y * blockDim.x + threadIdx.x; j < end;
         j += gridDim.y * blockDim.x) {
        int p = g_perm[j];
        float xv = __ldg(&x[p]);
        float ld = 0.f;
        const float* drow = delta + (size_t)p * SUMH;

        level_eval<128, 0>(xv, ld, drow, sE, sB);
        level_eval<64, 128>(xv, ld, drow, sE, sB);
        level_eval<32, 192>(xv, ld, drow, sE, sB);

        out[p] = xv;
        out[NP + p] = ld;
    }
}

// ---------------- launch ----------------
extern "C" void kernel_launch(void* const* d_in, const int* in_sizes, int n_in,
                              void* d_out, int out_size) {
    const float* x     = (const float*)d_in[0];
    const int*   roi   = (const int*)d_in[1];
    const int*   lrix  = (const int*)d_in[2];
    const float* delta = (const float*)d_in[3];
    const float* hemb  = (const float*)d_in[4];
    const float* wemb  = (const float*)d_in[5];
    float* out = (float*)d_out;

    k_zero<<<2, 256>>>();
    k_hist<<<NP / 256, 256>>>(lrix);
    k_scan<<<1, 512>>>();
    k_scatter<<<NP / 256, 256>>>(lrix);
    k_prep<<<NR_OI, 32>>>(roi, hemb, wemb);
    k_main<<<dim3(NR_OI, 4), 128>>>(x, delta, out);
}

// round 2
// speedup vs baseline: 1.5573x; 1.5573x over previous
#include <cuda_runtime.h>

#define NP 262144
#define NR_OI 500
#define SUMH 224
#define SUMW 221
#define SCAT_BLOCKS 128
#define SCAT_THREADS 256
#define CHUNK (NP / SCAT_BLOCKS)   // 2048

// ---------------- device scratch (no allocations allowed) ----------------
__device__ int    g_counts[NR_OI];
__device__ int    g_offsets[NR_OI + 1];
__device__ int    g_cursor[NR_OI];
__device__ int    g_perm[NP];
__device__ float2 g_ehw[NR_OI][SUMH];    // {exp(heights_emb), softmax width}
__device__ float  g_binloc[NR_OI][SUMH]; // bin locations per level-concat k

// ---------------- grouping pre-pass ----------------
__global__ void k_zero() {
    int t = blockIdx.x * blockDim.x + threadIdx.x;
    if (t < NR_OI) g_counts[t] = 0;
}

// smem-aggregated histogram
__global__ void __launch_bounds__(SCAT_THREADS)
k_hist(const int* __restrict__ lrix) {
    __shared__ int sc[NR_OI];
    for (int t = threadIdx.x; t < NR_OI; t += blockDim.x) sc[t] = 0;
    __syncthreads();
    int base = blockIdx.x * CHUNK;
    for (int j = threadIdx.x; j < CHUNK; j += blockDim.x)
        atomicAdd(&sc[lrix[base + j]], 1);
    __syncthreads();
    for (int t = threadIdx.x; t < NR_OI; t += blockDim.x) {
        int c = sc[t];
        if (c) atomicAdd(&g_counts[t], c);
    }
}

__global__ void k_scan() {
    __shared__ int s[512];
    int t = threadIdx.x;
    int v = (t < NR_OI) ? g_counts[t] : 0;
    s[t] = v;
    __syncthreads();
    for (int o = 1; o < 512; o <<= 1) {
        int a = (t >= o) ? s[t - o] : 0;
        __syncthreads();
        s[t] += a;
        __syncthreads();
    }
    if (t < NR_OI) {
        int ex = s[t] - v;
        g_offsets[t] = ex;
        g_cursor[t] = ex;
    }
    if (t == NR_OI - 1) g_offsets[NR_OI] = s[t];
}

// block-aggregated scatter: reserve per-region chunks, then rank locally
__global__ void __launch_bounds__(SCAT_THREADS)
k_scatter(const int* __restrict__ lrix) {
    __shared__ int sc[NR_OI];    // local counts, then local cursors
    __shared__ int sbase[NR_OI]; // global base for this block's chunk
    for (int t = threadIdx.x; t < NR_OI; t += blockDim.x) sc[t] = 0;
    __syncthreads();
    int base = blockIdx.x * CHUNK;
    for (int j = threadIdx.x; j < CHUNK; j += blockDim.x)
        atomicAdd(&sc[lrix[base + j]], 1);
    __syncthreads();
    for (int t = threadIdx.x; t < NR_OI; t += blockDim.x) {
        int c = sc[t];
        sbase[t] = c ? atomicAdd(&g_cursor[t], c) : 0;
        sc[t] = 0;
    }
    __syncthreads();
    for (int j = threadIdx.x; j < CHUNK; j += blockDim.x) {
        int i = base + j;
        int r = lrix[i];
        int rank = atomicAdd(&sc[r], 1);
        g_perm[sbase[r] + rank] = i;
    }
}

// ---------------- per-region table prep ----------------
__device__ __forceinline__ float warp_max(float v) {
#pragma unroll
    for (int o = 16; o; o >>= 1) v = fmaxf(v, __shfl_xor_sync(0xffffffffu, v, o));
    return v;
}
__device__ __forceinline__ float warp_sum(float v) {
#pragma unroll
    for (int o = 16; o; o >>= 1) v += __shfl_xor_sync(0xffffffffu, v, o);
    return v;
}

template <int N, int OH, int OW>
__device__ __forceinline__ void prep_level(int r, int rid,
                                           const float* __restrict__ hemb,
                                           const float* __restrict__ wemb,
                                           float* sw) {
    const int M = N - 1;
    int lane = threadIdx.x;

    float vals[4];
    float mx = -1e30f;
#pragma unroll
    for (int j = 0; j < 4; j++) {
        int k = lane + 32 * j;
        vals[j] = (k < M) ? wemb[(size_t)rid * SUMW + OW + k] : -1e30f;
        mx = fmaxf(mx, vals[j]);
    }
    mx = warp_max(mx);

    float es[4];
    float sum = 0.f;
#pragma unroll
    for (int j = 0; j < 4; j++) {
        int k = lane + 32 * j;
        es[j] = (k < M) ? __expf(vals[j] - mx) : 0.f;
        sum += es[j];
    }
    sum = warp_sum(sum);
    float inv = 1.f / sum;

#pragma unroll
    for (int j = 0; j < 4; j++) {
        int k = lane + 32 * j;
        if (k < M) sw[k] = es[j] * inv;
    }
    __syncwarp();

#pragma unroll
    for (int j = 0; j < 4; j++) {
        int k = lane + 32 * j;
        if (k < N) {
            float eh = __expf(hemb[(size_t)rid * SUMH + OH + k]);
            float wk = (k < M) ? sw[k] : 0.f;
            g_ehw[r][OH + k] = make_float2(eh, wk);
        }
    }

    if (lane == 0) {
        float c = 0.f;
        g_binloc[r][OH] = 0.f;
        for (int k = 1; k < N; k++) {
            c += sw[k - 1];
            g_binloc[r][OH + k] = (k == N - 1) ? 1.f : c;
        }
    }
    __syncwarp();
}

__global__ void k_prep(const int* __restrict__ roi,
                       const float* __restrict__ hemb,
                       const float* __restrict__ wemb) {
    __shared__ float sw[128];
    int r = blockIdx.x;
    int rid = roi[r];
    prep_level<128, 0, 0>(r, rid, hemb, wemb, sw);
    prep_level<64, 128, 127>(r, rid, hemb, wemb, sw);
    prep_level<32, 192, 190>(r, rid, hemb, wemb, sw);
}

// ---------------- main per-point kernel ----------------
template <int N, int OFF>
__device__ __forceinline__ void level_eval(float& xv, float& ld,
                                           const float* __restrict__ drow,
                                           const float2* __restrict__ sE,
                                           const float* __restrict__ sB) {
    const float2* E = sE + OFF;
    const float*  B = sB + OFF;

    // bin = clip(#(binloc < x) - 1, 0, N-2) via binary search on smem
    int lo = 0, hi = N;
    while (lo < hi) {
        int mid = (lo + hi) >> 1;
        if (B[mid] < xv) lo = mid + 1; else hi = mid;
    }
    int bin = lo - 1;
    bin = bin < 0 ? 0 : bin;
    bin = bin > N - 2 ? N - 2 : bin;

    const float4* d4 = reinterpret_cast<const float4*>(drow + OFF);

    float total = 0.f, partial = 0.f;
    float heprev = 0.f, wprev = 0.f;  // wprev=0 zeroes the bogus first term

#pragma unroll 4
    for (int c = 0; c < N / 4; c++) {
        float4 dv = __ldg(&d4[c]);
        float dd[4] = {dv.x, dv.y, dv.z, dv.w};
#pragma unroll
        for (int j = 0; j < 4; j++) {
            int k = 4 * c + j;
            float2 e = E[k];
            float he = e.x * __expf(dd[j]);
            float t = (heprev + he) * wprev;  // raw trapezoid term (2x actual)
            total += t;
            partial += (k <= bin) ? t : 0.f;  // (k-1) < bin
            heprev = he;
            wprev = e.y;
        }
    }

    // recompute edge heights (L1-hit loads + 2 MUFU, once per level)
    float hl = E[bin].x     * __expf(__ldg(&drow[OFF + bin]));
    float hr = E[bin + 1].x * __expf(__ldg(&drow[OFF + bin + 1]));

    float inv_t = __fdividef(1.f, total);
    float Hl = 2.f * hl * inv_t;
    float Hr = 2.f * hr * inv_t;
    float incdf = partial * inv_t;
    float inloc = B[bin];
    float w = E[bin].y;
    float alpha = (xv - inloc) * __fdividef(1.f, w);
    float dh = Hr - Hl;
    xv = (0.5f * dh * alpha + Hl) * (w * alpha) + incdf;
    ld += __logf(fmaf(alpha, dh, Hl));
}

__global__ void __launch_bounds__(128)
k_main(const float* __restrict__ x,
       const float* __restrict__ delta,
       float* __restrict__ out) {
    __shared__ float2 sE[SUMH];
    __shared__ float  sB[SUMH];

    int r = blockIdx.x;
    for (int i = threadIdx.x; i < SUMH; i += blockDim.x) {
        sE[i] = g_ehw[r][i];
        sB[i] = g_binloc[r][i];
    }
    __syncthreads();

    int beg = g_offsets[r];
    int end = g_offsets[r + 1];

    for (int j = beg + blockIdx.y * blockDim.x + threadIdx.x; j < end;
         j += gridDim.y * blockDim.x) {
        int p = g_perm[j];
        float xv = __ldg(&x[p]);
        float ld = 0.f;
        const float* drow = delta + (size_t)p * SUMH;

        level_eval<128, 0>(xv, ld, drow, sE, sB);
        level_eval<64, 128>(xv, ld, drow, sE, sB);
        level_eval<32, 192>(xv, ld, drow, sE, sB);

        out[p] = xv;
        out[NP + p] = ld;
    }
}

// ---------------- launch ----------------
extern "C" void kernel_launch(void* const* d_in, const int* in_sizes, int n_in,
                              void* d_out, int out_size) {
    const float* x     = (const float*)d_in[0];
    const int*   roi   = (const int*)d_in[1];
    const int*   lrix  = (const int*)d_in[2];
    const float* delta = (const float*)d_in[3];
    const float* hemb  = (const float*)d_in[4];
    const float* wemb  = (const float*)d_in[5];
    float* out = (float*)d_out;

    k_zero<<<2, 256>>>();
    k_hist<<<SCAT_BLOCKS, SCAT_THREADS>>>(lrix);
    k_scan<<<1, 512>>>();
    k_scatter<<<SCAT_BLOCKS, SCAT_THREADS>>>(lrix);
    k_prep<<<NR_OI, 32>>>(roi, hemb, wemb);
    k_main<<<dim3(NR_OI, 4), 128>>>(x, delta, out);
}

// round 3
// speedup vs baseline: 1.9660x; 1.2625x over previous
#include <cuda_runtime.h>

#define NP 262144
#define NR_OI 500
#define SUMH 224
#define SUMW 221
#define SCAT_BLOCKS 128
#define SCAT_THREADS 256
#define CHUNK (NP / SCAT_BLOCKS)   // 2048
#define LOG2E 1.4426950408889634f

// ---------------- device scratch (no allocations allowed) ----------------
__device__ int   g_counts[NR_OI];
__device__ int   g_offsets[NR_OI + 1];
__device__ int   g_cursor[NR_OI];
__device__ int   g_perm[NP];
__device__ float g_lemb[NR_OI][SUMH];   // log2e * heights_emb
__device__ float g_cw[NR_OI][SUMH];     // w[k-1] + w[k]  (edges 0)
__device__ float g_w[NR_OI][SUMH];      // softmax widths (w[N-1]=0 pad)
__device__ float g_binloc[NR_OI][SUMH]; // bin locations

__device__ __forceinline__ float ex2f(float a) {
    float r;
    asm("ex2.approx.ftz.f32 %0, %1;" : "=f"(r) : "f"(a));
    return r;
}

// ---------------- grouping pre-pass ----------------
__global__ void k_zero() {
    int t = blockIdx.x * blockDim.x + threadIdx.x;
    if (t < NR_OI) g_counts[t] = 0;
}

__global__ void __launch_bounds__(SCAT_THREADS)
k_hist(const int* __restrict__ lrix) {
    __shared__ int sc[NR_OI];
    for (int t = threadIdx.x; t < NR_OI; t += blockDim.x) sc[t] = 0;
    __syncthreads();
    int base = blockIdx.x * CHUNK;
    for (int j = threadIdx.x; j < CHUNK; j += blockDim.x)
        atomicAdd(&sc[lrix[base + j]], 1);
    __syncthreads();
    for (int t = threadIdx.x; t < NR_OI; t += blockDim.x) {
        int c = sc[t];
        if (c) atomicAdd(&g_counts[t], c);
    }
}

__global__ void k_scan() {
    __shared__ int s[512];
    int t = threadIdx.x;
    int v = (t < NR_OI) ? g_counts[t] : 0;
    s[t] = v;
    __syncthreads();
    for (int o = 1; o < 512; o <<= 1) {
        int a = (t >= o) ? s[t - o] : 0;
        __syncthreads();
        s[t] += a;
        __syncthreads();
    }
    if (t < NR_OI) {
        int ex = s[t] - v;
        g_offsets[t] = ex;
        g_cursor[t] = ex;
    }
    if (t == NR_OI - 1) g_offsets[NR_OI] = s[t];
}

__global__ void __launch_bounds__(SCAT_THREADS)
k_scatter(const int* __restrict__ lrix) {
    __shared__ int sc[NR_OI];
    __shared__ int sbase[NR_OI];
    for (int t = threadIdx.x; t < NR_OI; t += blockDim.x) sc[t] = 0;
    __syncthreads();
    int base = blockIdx.x * CHUNK;
    for (int j = threadIdx.x; j < CHUNK; j += blockDim.x)
        atomicAdd(&sc[lrix[base + j]], 1);
    __syncthreads();
    for (int t = threadIdx.x; t < NR_OI; t += blockDim.x) {
        int c = sc[t];
        sbase[t] = c ? atomicAdd(&g_cursor[t], c) : 0;
        sc[t] = 0;
    }
    __syncthreads();
    for (int j = threadIdx.x; j < CHUNK; j += blockDim.x) {
        int i = base + j;
        int r = lrix[i];
        int rank = atomicAdd(&sc[r], 1);
        g_perm[sbase[r] + rank] = i;
    }
}

// ---------------- per-region table prep ----------------
__device__ __forceinline__ float warp_max(float v) {
#pragma unroll
    for (int o = 16; o; o >>= 1) v = fmaxf(v, __shfl_xor_sync(0xffffffffu, v, o));
    return v;
}
__device__ __forceinline__ float warp_sum(float v) {
#pragma unroll
    for (int o = 16; o; o >>= 1) v += __shfl_xor_sync(0xffffffffu, v, o);
    return v;
}

template <int N, int OH, int OW>
__device__ __forceinline__ void prep_level(int r, int rid,
                                           const float* __restrict__ hemb,
                                           const float* __restrict__ wemb,
                                           float* sw) {
    const int M = N - 1;
    int lane = threadIdx.x;

    float vals[4];
    float mx = -1e30f;
#pragma unroll
    for (int j = 0; j < 4; j++) {
        int k = lane + 32 * j;
        vals[j] = (k < M) ? wemb[(size_t)rid * SUMW + OW + k] : -1e30f;
        mx = fmaxf(mx, vals[j]);
    }
    mx = warp_max(mx);

    float es[4];
    float sum = 0.f;
#pragma unroll
    for (int j = 0; j < 4; j++) {
        int k = lane + 32 * j;
        es[j] = (k < M) ? __expf(vals[j] - mx) : 0.f;
        sum += es[j];
    }
    sum = warp_sum(sum);
    float inv = 1.f / sum;

#pragma unroll
    for (int j = 0; j < 4; j++) {
        int k = lane + 32 * j;
        if (k < M) sw[k] = es[j] * inv;
    }
    __syncwarp();

#pragma unroll
    for (int j = 0; j < 4; j++) {
        int k = lane + 32 * j;
        if (k < N) {
            float wk = (k < M) ? sw[k] : 0.f;
            float wkm1 = (k > 0) ? sw[k - 1] : 0.f;
            g_w[r][OH + k] = wk;
            g_cw[r][OH + k] = wk + wkm1;
            g_lemb[r][OH + k] = LOG2E * hemb[(size_t)rid * SUMH + OH + k];
        }
    }

    if (lane == 0) {
        float c = 0.f;
        g_binloc[r][OH] = 0.f;
        for (int k = 1; k < N; k++) {
            c += sw[k - 1];
            g_binloc[r][OH + k] = (k == N - 1) ? 1.f : c;
        }
    }
    __syncwarp();
}

__global__ void k_prep(const int* __restrict__ roi,
                       const float* __restrict__ hemb,
                       const float* __restrict__ wemb) {
    __shared__ float sw[128];
    int r = blockIdx.x;
    int rid = roi[r];
    prep_level<128, 0, 0>(r, rid, hemb, wemb, sw);
    prep_level<64, 128, 127>(r, rid, hemb, wemb, sw);
    prep_level<32, 192, 190>(r, rid, hemb, wemb, sw);
}

// ---------------- main per-point kernel ----------------
// 8 lanes cooperate on one point; 4 points per warp.
template <int N, int OFF, int STEPS>
__device__ __forceinline__ void level_eval(float& xv, float& ld, int g,
                                           const float* __restrict__ drow,
                                           const float* __restrict__ sL,
                                           const float* __restrict__ sC,
                                           const float* __restrict__ sW,
                                           const float* __restrict__ sB) {
    const float* L = sL + OFF;
    const float* C = sC + OFF;
    const float* B = sB + OFF;

    // branch-free search: pos = largest index with B[pos] < xv (0 if none)
    int pos = 0;
#pragma unroll
    for (int s = 0; s < STEPS; s++) {
        int step = N >> (s + 1);
        pos += (B[pos + step] < xv) ? step : 0;
    }
    int bin = pos > N - 2 ? N - 2 : pos;

    const float4* d4 = reinterpret_cast<const float4*>(drow + OFF);

    float total = 0.f, partial = 0.f;
#pragma unroll
    for (int i = 0; i < N / 32; i++) {
        int kb = g * 4 + i * 32;
        float4 dv = __ldg(&d4[g + i * 8]);
        float dd[4] = {dv.x, dv.y, dv.z, dv.w};
#pragma unroll
        for (int j = 0; j < 4; j++) {
            int k = kb + j;
            float he = ex2f(fmaf(dd[j], LOG2E, L[k]));
            float cw = C[k];
            total = fmaf(he, cw, total);
            float cwp = (k < bin) ? cw : 0.f;
            partial = fmaf(he, cwp, partial);
        }
    }

    // reduce over the 8-lane group (xor of bits 2,1,0 stays in-group)
#pragma unroll
    for (int o = 4; o; o >>= 1) {
        total += __shfl_xor_sync(0xffffffffu, total, o);
        partial += __shfl_xor_sync(0xffffffffu, partial, o);
    }

    // epilogue (all lanes identical)
    float hl = ex2f(fmaf(__ldg(&drow[OFF + bin]), LOG2E, L[bin]));
    float hr = ex2f(fmaf(__ldg(&drow[OFF + bin + 1]), LOG2E, L[bin + 1]));
    float wb = sW[OFF + bin];
    float wbm1 = C[bin] - wb;          // w[bin-1]
    partial += hl * wbm1;

    float inv_t = __fdividef(1.f, total);
    float Hl = 2.f * hl * inv_t;
    float Hr = 2.f * hr * inv_t;
    float incdf = partial * inv_t;
    float alpha = (xv - B[bin]) * __fdividef(1.f, wb);
    float dh = Hr - Hl;
    xv = (0.5f * dh * alpha + Hl) * (wb * alpha) + incdf;
    ld += __logf(fmaf(alpha, dh, Hl));
}

__global__ void __launch_bounds__(128)
k_main(const float* __restrict__ x,
       const float* __restrict__ delta,
       float* __restrict__ out) {
    __shared__ float sL[SUMH];
    __shared__ float sC[SUMH];
    __shared__ float sW[SUMH];
    __shared__ float sB[SUMH];

    int r = blockIdx.x;
    for (int i = threadIdx.x; i < SUMH; i += blockDim.x) {
        sL[i] = g_lemb[r][i];
        sC[i] = g_cw[r][i];
        sW[i] = g_w[r][i];
        sB[i] = g_binloc[r][i];
    }
    __syncthreads();

    int g = threadIdx.x & 7;                 // lane within 8-lane group
    int grpInBlock = threadIdx.x >> 3;       // 0..15
    int beg = g_offsets[r];
    int end = g_offsets[r + 1];
    int stride = gridDim.y * 16;

    for (int j = beg + blockIdx.y * 16 + grpInBlock; j < end; j += stride) {
        int p = g_perm[j];
        float xv = __ldg(&x[p]);
        float ld = 0.f;
        const float* drow = delta + (size_t)p * SUMH;

        level_eval<128, 0, 7>(xv, ld, g, drow, sL, sC, sW, sB);
        level_eval<64, 128, 6>(xv, ld, g, drow, sL, sC, sW, sB);
        level_eval<32, 192, 5>(xv, ld, g, drow, sL, sC, sW, sB);

        if (g == 0) {
            out[p] = xv;
            out[NP + p] = ld;
        }
    }
}

// ---------------- launch ----------------
extern "C" void kernel_launch(void* const* d_in, const int* in_sizes, int n_in,
                              void* d_out, int out_size) {
    const float* x     = (const float*)d_in[0];
    const int*   roi   = (const int*)d_in[1];
    const int*   lrix  = (const int*)d_in[2];
    const float* delta = (const float*)d_in[3];
    const float* hemb  = (const float*)d_in[4];
    const float* wemb  = (const float*)d_in[5];
    float* out = (float*)d_out;

    k_zero<<<2, 256>>>();
    k_hist<<<SCAT_BLOCKS, SCAT_THREADS>>>(lrix);
    k_scan<<<1, 512>>>();
    k_scatter<<<SCAT_BLOCKS, SCAT_THREADS>>>(lrix);
    k_prep<<<NR_OI, 32>>>(roi, hemb, wemb);
    k_main<<<dim3(NR_OI, 8), 128>>>(x, delta, out);
}